// round 13
// baseline (speedup 1.0000x reference)
#include <cuda_runtime.h>
#include <cuda_bf16.h>

#define NUM_CHIPS 4
#define N_EXPERTS 32
#define TOP_K 4
#define SEQ 1024
#define HIDDEN 2048
#define MAX_TOK 1024
#define META_LEN 8
#define NPC (SEQ * TOP_K)            /* 4096 assignments per chip  */
#define NA (NUM_CHIPS * NPC)         /* 16384 total assignments    */
#define NROWS (N_EXPERTS * MAX_TOK)  /* 32768 output rows          */
#define NWGRP (NA / 32)              /* 512 assignment warp-groups */

#define PLAN_BLOCKS 256
#define PLAN_THREADS 256

#define V4_PER_ROW (HIDDEN / 4)      /* 512 float4 per row  */
#define COPY_THREADS 128             /* one block per row; 4 float4/thread */

/* scratch — no allocations allowed; every used cell rewritten per run */
__device__ int g_wcnt[NWGRP * N_EXPERTS];   /* [wg][e] per-warp-group counts */
__device__ int g_woff[NWGRP * N_EXPERTS];   /* [wg][e] global exclusive pfx  */
__device__ int g_total[N_EXPERTS];
__device__ int2 g_pack[NROWS];              /* row -> {src | -1, assignment} */
__device__ unsigned g_bar;                  /* monotonic barrier counter     */

/* ------------------------------------------------------------------ */
/* Grid barrier across PLAN_BLOCKS co-resident blocks. Each launch adds
   exactly 2*PLAN_BLOCKS=512 arrivals, so base = old & ~511 is
   replay-deterministic with no reset. phase = 1 or 2.                 */
__device__ __forceinline__ void plan_barrier(int phase) {
    __syncthreads();
    if (threadIdx.x == 0) {
        __threadfence();
        const unsigned old = atomicAdd(&g_bar, 1u);
        const unsigned base = old & ~(2u * PLAN_BLOCKS - 1u);
        const unsigned target = base + (unsigned)phase * PLAN_BLOCKS;
        while (*(volatile unsigned*)&g_bar < target) {}
        __threadfence();
    }
    __syncthreads();
}

/* ------------------------------------------------------------------ */
/* Single plan kernel: 256 blocks x 256 threads, all wave-1 resident.
   P1: blocks 0..63  -> per-warp counts + intra-warp rank (registers).
   P2: blocks 64..95 -> per-expert scan of 512 groups -> woff/totals.
   P3: blocks 0..63  -> filled g_pack from registers;
       blocks 64..191 -> tail rows {-1,-1} (spread chip-wide).         */
__global__ void __launch_bounds__(PLAN_THREADS) k_plan(const int* __restrict__ indices,
                                                       float* __restrict__ out_cnt) {
    __shared__ int wsum[8];
    const int b = blockIdx.x, tid = threadIdx.x;
    const int lane = tid & 31;

    /* ---- P1: count + intra-warp stable rank ---- */
    int e = -1, lrank = 0;
    const int t = b * PLAN_THREADS + tid;            /* assignment id, b<64 */
    if (b < 64) {
        e = indices[t];
        const unsigned mask = __match_any_sync(0xffffffffu, e);
        lrank = __popc(mask & ((1u << lane) - 1u));
        int cnt = 0;
#pragma unroll
        for (int x = 0; x < N_EXPERTS; x++) {
            const unsigned m = __ballot_sync(0xffffffffu, e == x);
            if (lane == x) cnt = __popc(m);
        }
        g_wcnt[(t >> 5) * N_EXPERTS + lane] = cnt;   /* coalesced */
    }

    plan_barrier(1);

    /* ---- P2: per-expert exclusive scan over the 512 warp-groups ---- */
    if (b >= 64 && b < 64 + N_EXPERTS) {
        const int eb = b - 64;
        const int w = tid >> 5;
        const int v0 = g_wcnt[(tid * 2 + 0) * N_EXPERTS + eb];
        const int v1 = g_wcnt[(tid * 2 + 1) * N_EXPERTS + eb];
        const int s = v0 + v1;
        int incl = s;
#pragma unroll
        for (int d = 1; d < 32; d <<= 1) {
            const int n = __shfl_up_sync(0xffffffffu, incl, d);
            if (lane >= d) incl += n;
        }
        if (lane == 31) wsum[w] = incl;
        __syncthreads();
        int base = 0;
#pragma unroll
        for (int ww = 0; ww < 8; ww++) if (ww < w) base += wsum[ww];
        const int excl = base + incl - s;
        g_woff[(tid * 2 + 0) * N_EXPERTS + eb] = excl;
        g_woff[(tid * 2 + 1) * N_EXPERTS + eb] = excl + v0;
        if (tid == PLAN_THREADS - 1) {
            const int tot = base + incl;             /* grand total */
            g_total[eb] = tot;
            out_cnt[eb] = (float)tot;
        }
    }

    plan_barrier(2);

    /* ---- P3 ---- */
    if (b < 64) {                                    /* filled rows */
        const int c = t >> 12, n = t & (NPC - 1);
        const int tok = n >> 2;
        const int row = e * MAX_TOK + g_woff[(t >> 5) * N_EXPERTS + e] + lrank;
        g_pack[row] = make_int2(c * SEQ + tok, t);
    } else if (b < 64 + 128) {                       /* tail rows */
        const int row = (b - 64) * PLAN_THREADS + tid;
        const int ee = row >> 10, r = row & (MAX_TOK - 1);
        if (r >= g_total[ee]) g_pack[row] = make_int2(-1, -1);
    }
}

/* ------------------------------------------------------------------ */
/* Copy kernel: one 128-thread block per output row; emits row data AND
   its metadata (thread 0). Filled: 4 indep LDG chains + 4 STGs per
   thread. Zero: stores only. (Measured 51us @ DRAM 70% — ceiling.)    */
__global__ void __launch_bounds__(COPY_THREADS) k_copy(const float4* __restrict__ x4,
                                                       const float* __restrict__ wts,
                                                       float* __restrict__ meta,
                                                       float4* __restrict__ buf4) {
    const unsigned row = blockIdx.x;
    const unsigned t = threadIdx.x;
    const int2 p = __ldg(&g_pack[row]);              /* broadcast */
    float4* dst = buf4 + row * V4_PER_ROW + t;

    if (p.x >= 0) {
        const float4* src = x4 + (unsigned)p.x * V4_PER_ROW + t;
        float4 v0 = __ldg(&src[0 * COPY_THREADS]);
        float4 v1 = __ldg(&src[1 * COPY_THREADS]);
        float4 v2 = __ldg(&src[2 * COPY_THREADS]);
        float4 v3 = __ldg(&src[3 * COPY_THREADS]);
        dst[0 * COPY_THREADS] = v0;
        dst[1 * COPY_THREADS] = v1;
        dst[2 * COPY_THREADS] = v2;
        dst[3 * COPY_THREADS] = v3;
        if (t == 0) {
            const int a = p.y;
            const int c = a >> 12, n = a & (NPC - 1);
            const int tok = n >> 2, kk = n & (TOP_K - 1);
            const int e = (int)(row >> 10);
            __nv_bfloat16 wb = __float2bfloat16(__ldg(&wts[a]));  /* RNE */
            const int bits = (int)__bfloat16_as_short(wb);        /* sext */
            float4* m = (float4*)(meta + (size_t)row * META_LEN);
            m[0] = make_float4((float)c, (float)tok, (float)kk, (float)e);
            m[1] = make_float4((float)bits, 0.f, 0.f, 0.f);
        }
    } else {
        const float4 z = make_float4(0.f, 0.f, 0.f, 0.f);
        dst[0 * COPY_THREADS] = z;
        dst[1 * COPY_THREADS] = z;
        dst[2 * COPY_THREADS] = z;
        dst[3 * COPY_THREADS] = z;
        if (t == 0) {
            float4* m = (float4*)(meta + (size_t)row * META_LEN);
            const float4 neg = make_float4(-1.f, -1.f, -1.f, -1.f);
            m[0] = neg; m[1] = neg;
        }
    }
}

/* ------------------------------------------------------------------ */
extern "C" void kernel_launch(void* const* d_in, const int* in_sizes, int n_in,
                              void* d_out, int out_size) {
    const float* x   = (const float*)d_in[0];
    const float* w   = (const float*)d_in[1];
    const int*   idx = (const int*)d_in[2];

    float* out  = (float*)d_out;
    float* buf  = out;                                                   /* 32*1024*2048 */
    float* meta = out + (size_t)NROWS * HIDDEN;                          /* 32*1024*8    */
    float* cnt  = meta + (size_t)NROWS * META_LEN;                       /* 32           */

    k_plan<<<PLAN_BLOCKS, PLAN_THREADS>>>(idx, cnt);
    k_copy<<<NROWS, COPY_THREADS>>>((const float4*)x, w, meta, (float4*)buf);
}